// round 1
// baseline (speedup 1.0000x reference)
#include <cuda_runtime.h>
#include <cstdint>
#include <cstddef>

#define H     2048
#define SEQ   4096
#define NCTA  128
#define TPB   256
#define NWARP 8
#define UPC   16            // hidden units per CTA (H / NCTA)
#define SROWS_PW 3          // smem-resident rows per warp
#define SROWS (NWARP * SROWS_PW)          // 24 rows in smem per CTA
#define SMEM_FLOATS (H + SROWS * H)       // h tile + weight rows
#define SMEM_BYTES  (SMEM_FLOATS * 4)     // 204800 B

// Persistent scratch (no allocations allowed in kernel_launch)
__device__ float    g_h[2][H];
__device__ float    g_py[(size_t)NCTA * SEQ];
__device__ unsigned g_count = 0;
__device__ volatile unsigned g_gen = 0;

__device__ __forceinline__ float sigm_f(float z) {
    return 1.f / (1.f + __expf(-z));
}
__device__ __forceinline__ float tanh_f(float z) {
    z = fminf(20.f, fmaxf(-20.f, z));
    float e = __expf(2.f * z);
    return (e - 1.f) / (e + 1.f);
}

__global__ void __launch_bounds__(TPB, 1)
lstm_persistent(const float* __restrict__ inputs,
                const float* __restrict__ w_ih,
                const float* __restrict__ w_hh,
                const float* __restrict__ b_ih,
                const float* __restrict__ b_hh,
                const float* __restrict__ w_out,
                float* __restrict__ out)
{
    extern __shared__ float smem[];
    float* smH = smem;          // H floats
    float* smW = smem + H;      // SROWS * H floats
    __shared__ float s_x;
    __shared__ float s_ypart[NWARP];

    const int tid  = threadIdx.x;
    const int lane = tid & 31;
    const int w    = tid >> 5;
    const int cta  = blockIdx.x;
    const int ubase = cta * UPC + 2 * w;   // first unit owned by this warp

    // Read barrier generation base BEFORE any arrival (monotonic across graph replays).
    unsigned base_gen = 0;
    if (tid == 0) base_gen = g_gen;

    // ---- one-time preload of smem-resident weight rows ----
    // warp ww keeps rows (unit = cta*UPC + 2*ww, gates k=0..2) in smem
    for (int idx = tid; idx < SROWS * H; idx += TPB) {
        int rl  = idx >> 11;          // row-local (H = 2048)
        int col = idx & (H - 1);
        int ww  = rl / SROWS_PW;
        int k   = rl - ww * SROWS_PW;
        int grow = cta * UPC + 2 * ww + k * H;
        smW[idx] = w_hh[(size_t)grow * H + col];
    }

    // ---- per gate-lane constants (lanes 0,1 own units ubase+0, ubase+1) ----
    float wx0=0,wx1=0,wx2=0,wx3=0, bb0=0,bb1=0,bb2=0,bb3=0, wo=0;
    float c_st = 0.f, h_last = 0.f;
    if (lane < 2) {
        int ug = ubase + lane;
        wx0 = w_ih[ug];         bb0 = b_ih[ug]       + b_hh[ug];
        wx1 = w_ih[ug +   H];   bb1 = b_ih[ug +   H] + b_hh[ug +   H];
        wx2 = w_ih[ug + 2*H];   bb2 = b_ih[ug + 2*H] + b_hh[ug + 2*H];
        wx3 = w_ih[ug + 3*H];   bb3 = b_ih[ug + 3*H] + b_hh[ug + 3*H];
        wo  = w_out[ug];
    }

    // zero h buffer 0 for our units (fresh every launch / graph replay)
    if (tid < UPC) g_h[0][cta * UPC + tid] = 0.f;

    // ---- grid barrier 0: publish zeros ----
    __threadfence();
    __syncthreads();
    if (tid == 0) {
        unsigned tgt  = base_gen + 1;
        unsigned prev = atomicAdd(&g_count, 1u);
        if (prev == NCTA - 1) { g_count = 0; __threadfence(); g_gen = tgt; }
        else { while (g_gen != tgt) __nanosleep(64); }
    }
    __syncthreads();

    // streamed rows for this warp: (L=0,g=3) and (L=1,g=0..3)
    const float4* wrow3 = (const float4*)(w_hh + (size_t)(ubase + 0 + 3*H) * H);
    const float4* wrow4 = (const float4*)(w_hh + (size_t)(ubase + 1 + 0*H) * H);
    const float4* wrow5 = (const float4*)(w_hh + (size_t)(ubase + 1 + 1*H) * H);
    const float4* wrow6 = (const float4*)(w_hh + (size_t)(ubase + 1 + 2*H) * H);
    const float4* wrow7 = (const float4*)(w_hh + (size_t)(ubase + 1 + 3*H) * H);
    const float4* smH4   = (const float4*)smH;
    const float4* smW4_0 = (const float4*)(smW + (w * SROWS_PW + 0) * H);
    const float4* smW4_1 = (const float4*)(smW + (w * SROWS_PW + 1) * H);
    const float4* smW4_2 = (const float4*)(smW + (w * SROWS_PW + 2) * H);

    for (int t = 0; t < SEQ; ++t) {
        const int p = t & 1;

        // stage h_{t-1} into smem (must bypass L1: written by other SMs)
        {
            const float4* hsrc = (const float4*)g_h[p];
            float4 v0 = __ldcg(&hsrc[tid]);
            float4 v1 = __ldcg(&hsrc[tid + TPB]);
            ((float4*)smH)[tid]       = v0;
            ((float4*)smH)[tid + TPB] = v1;
        }
        if (tid == 0) s_x = __ldcg(&inputs[t]);
        __syncthreads();

        // ---- 8 row dot-products, h-outer so each h float4 is loaded once ----
        float4 acc[8];
        #pragma unroll
        for (int r = 0; r < 8; ++r) acc[r] = make_float4(0.f, 0.f, 0.f, 0.f);

        #pragma unroll
        for (int cc = 0; cc < 16; ++cc) {
            const int o = cc * 32 + lane;
            float4 hv = smH4[o];
            float4 wv[8];
            wv[0] = smW4_0[o];
            wv[1] = smW4_1[o];
            wv[2] = smW4_2[o];
            wv[3] = __ldcg(&wrow3[o]);
            wv[4] = __ldcg(&wrow4[o]);
            wv[5] = __ldcg(&wrow5[o]);
            wv[6] = __ldcg(&wrow6[o]);
            wv[7] = __ldcg(&wrow7[o]);
            #pragma unroll
            for (int r = 0; r < 8; ++r) {
                acc[r].x = fmaf(wv[r].x, hv.x, acc[r].x);
                acc[r].y = fmaf(wv[r].y, hv.y, acc[r].y);
                acc[r].z = fmaf(wv[r].z, hv.z, acc[r].z);
                acc[r].w = fmaf(wv[r].w, hv.w, acc[r].w);
            }
        }

        float rs[8];
        #pragma unroll
        for (int r = 0; r < 8; ++r) {
            float s = (acc[r].x + acc[r].y) + (acc[r].z + acc[r].w);
            #pragma unroll
            for (int o2 = 16; o2; o2 >>= 1)
                s += __shfl_xor_sync(0xffffffffu, s, o2);
            rs[r] = s;
        }

        // ---- gates: lane L in {0,1} owns unit ubase+L ----
        if (lane < 2) {
            float x  = s_x;
            float zi = (lane ? rs[4] : rs[0]) + x * wx0 + bb0;
            float zf = (lane ? rs[5] : rs[1]) + x * wx1 + bb1;
            float zg = (lane ? rs[6] : rs[2]) + x * wx2 + bb2;
            float zo = (lane ? rs[7] : rs[3]) + x * wx3 + bb3;
            float ig = sigm_f(zi);
            float fg = sigm_f(zf);
            float gg = tanh_f(zg);
            float og = sigm_f(zo);
            c_st = fg * c_st + ig * gg;
            float hn = og * tanh_f(c_st);
            h_last = hn;
            g_h[p ^ 1][ubase + lane] = hn;
            float py = wo * hn;
            py += __shfl_xor_sync(0x3u, py, 1);
            if (lane == 0) s_ypart[w] = py;
        }
        __syncthreads();

        // ---- publish h, partial y; grid barrier ----
        if (tid == 0) {
            float s = 0.f;
            #pragma unroll
            for (int i = 0; i < NWARP; ++i) s += s_ypart[i];
            g_py[(size_t)cta * SEQ + t] = s;

            __threadfence();
            unsigned tgt  = base_gen + 2 + (unsigned)t;
            unsigned prev = atomicAdd(&g_count, 1u);
            if (prev == NCTA - 1) { g_count = 0; __threadfence(); g_gen = tgt; }
            else { while (g_gen != tgt) __nanosleep(64); }
        }
        __syncthreads();
    }

    // final h, c
    if (lane < 2) {
        int ug = ubase + lane;
        out[SEQ + ug]     = h_last;
        out[SEQ + H + ug] = c_st;
    }
}

__global__ void reduce_y(const float* __restrict__ b_out, float* __restrict__ out)
{
    int t = blockIdx.x * blockDim.x + threadIdx.x;
    float s = b_out[0];
    #pragma unroll 8
    for (int b = 0; b < NCTA; ++b)
        s += g_py[(size_t)b * SEQ + t];   // fixed order -> deterministic
    out[t] = s;
}

extern "C" void kernel_launch(void* const* d_in, const int* in_sizes, int n_in,
                              void* d_out, int out_size)
{
    (void)in_sizes; (void)n_in; (void)out_size;
    const float* inputs = (const float*)d_in[0];
    const float* w_ih   = (const float*)d_in[1];
    const float* w_hh   = (const float*)d_in[2];
    const float* b_ih   = (const float*)d_in[3];
    const float* b_hh   = (const float*)d_in[4];
    const float* w_out  = (const float*)d_in[5];
    const float* b_out  = (const float*)d_in[6];
    float* out = (float*)d_out;

    cudaFuncSetAttribute(lstm_persistent,
                         cudaFuncAttributeMaxDynamicSharedMemorySize, SMEM_BYTES);

    lstm_persistent<<<NCTA, TPB, SMEM_BYTES>>>(inputs, w_ih, w_hh, b_ih, b_hh,
                                               w_out, out);
    reduce_y<<<SEQ / 256, 256>>>(b_out, out);
}

// round 4
// speedup vs baseline: 1.1601x; 1.1601x over previous
#include <cuda_runtime.h>
#include <cstdint>
#include <cstddef>

#define H     2048
#define SEQ   4096
#define NCTA  128
#define TPB   256
#define NWARP 8
#define UPC   16            // hidden units per CTA (H / NCTA)
#define SROWS 27                          // smem-resident weight rows per CTA
#define SMEM_FLOATS (H + SROWS * H)       // h tile + weight rows
#define SMEM_BYTES  (SMEM_FLOATS * 4)     // 229376 B (max dyn smem 232448)

// Persistent scratch (no allocations allowed anywhere)
__device__ float    g_h[2][H];
__device__ float    g_py[(size_t)NCTA * SEQ];
__device__ unsigned g_count = 0;
__device__ volatile unsigned g_gen = 0;

__device__ __forceinline__ float sigm_f(float z) {
    return 1.f / (1.f + __expf(-z));
}
__device__ __forceinline__ float tanh_f(float z) {
    z = fminf(20.f, fmaxf(-20.f, z));
    float e = __expf(2.f * z);
    return (e - 1.f) / (e + 1.f);
}

__global__ void __launch_bounds__(TPB, 1)
lstm_persistent(const float* __restrict__ inputs,
                const float* __restrict__ w_ih,
                const float* __restrict__ w_hh,
                const float* __restrict__ b_ih,
                const float* __restrict__ b_hh,
                const float* __restrict__ w_out,
                float* __restrict__ out)
{
    extern __shared__ float smem[];
    float* smH = smem;          // H floats
    float* smW = smem + H;      // SROWS * H floats
    __shared__ float s_x;
    __shared__ float s_ypart[NWARP];

    const int tid  = threadIdx.x;
    const int lane = tid & 31;
    const int w    = tid >> 5;
    const int cta  = blockIdx.x;
    const int ubase = cta * UPC + 2 * w;   // first unit owned by this warp

    // Read barrier generation base BEFORE any arrival (monotonic across replays).
    unsigned base_gen = 0;
    if (tid == 0) base_gen = g_gen;

    // ---- one-time preload of smem-resident weight rows ----
    // rows 0..23 : warp ww keeps gates k=0..2 of unit (cta*UPC + 2*ww)   [r0..r2]
    // rows 24..26: warps j=0..2 keep gate 1 of unit (cta*UPC + 2*j + 1)  [their r5]
    for (int idx = tid; idx < SROWS * H; idx += TPB) {
        int rl  = idx >> 11;          // row-local (H = 2048)
        int col = idx & (H - 1);
        int grow;
        if (rl < 24) {
            int ww = rl / 3;
            int k  = rl - ww * 3;
            grow = k * H + (cta * UPC + 2 * ww);
        } else {
            int j = rl - 24;
            grow = 1 * H + (cta * UPC + 2 * j + 1);
        }
        smW[idx] = w_hh[(size_t)grow * H + col];
    }

    // ---- per gate-lane constants (lanes 0,1 own units ubase+0, ubase+1) ----
    float wx0=0,wx1=0,wx2=0,wx3=0, bb0=0,bb1=0,bb2=0,bb3=0, wo=0;
    float c_st = 0.f, h_last = 0.f;
    if (lane < 2) {
        int ug = ubase + lane;
        wx0 = w_ih[ug];         bb0 = b_ih[ug]       + b_hh[ug];
        wx1 = w_ih[ug +   H];   bb1 = b_ih[ug +   H] + b_hh[ug +   H];
        wx2 = w_ih[ug + 2*H];   bb2 = b_ih[ug + 2*H] + b_hh[ug + 2*H];
        wx3 = w_ih[ug + 3*H];   bb3 = b_ih[ug + 3*H] + b_hh[ug + 3*H];
        wo  = w_out[ug];
    }

    // zero h buffer 0 for our units (fresh every launch / graph replay)
    if (tid < UPC) g_h[0][cta * UPC + tid] = 0.f;

    // ---- grid barrier 0: publish zeros (proven R1 barrier) ----
    __threadfence();
    __syncthreads();
    if (tid == 0) {
        unsigned tgt  = base_gen + 1;
        unsigned prev = atomicAdd(&g_count, 1u);
        if (prev == NCTA - 1) { g_count = 0; __threadfence(); g_gen = tgt; }
        else { while (g_gen != tgt) __nanosleep(32); }
    }
    __syncthreads();

    // Row map per warp (8 rows r = L*4 + gate, L = unit-local):
    //   r0..r2 : smem   (L0 g0..g2)
    //   r3,r4  : regs   (L0 g3, L1 g0)
    //   r5     : smem for warps 0..2, streamed for warps 3..7 (L1 g1)
    //   r6,r7  : streamed (L1 g2,g3)
    const float4* wrow3 = (const float4*)(w_hh + (size_t)(3*H + ubase + 0) * H);
    const float4* wrow4 = (const float4*)(w_hh + (size_t)(0*H + ubase + 1) * H);
    const float4* wrow5 = (const float4*)(w_hh + (size_t)(1*H + ubase + 1) * H);
    const float4* wrow6 = (const float4*)(w_hh + (size_t)(2*H + ubase + 1) * H);
    const float4* wrow7 = (const float4*)(w_hh + (size_t)(3*H + ubase + 1) * H);

    // ---- one-time load of register-resident rows (128 regs/thread) ----
    float4 rw3q[16], rw4q[16];
    #pragma unroll
    for (int cc = 0; cc < 16; ++cc) {
        rw3q[cc] = __ldg(&wrow3[cc * 32 + lane]);
        rw4q[cc] = __ldg(&wrow4[cc * 32 + lane]);
    }

    const float4* smH4   = (const float4*)smH;
    const float4* smW4_0 = (const float4*)(smW + (w * 3 + 0) * H);
    const float4* smW4_1 = (const float4*)(smW + (w * 3 + 1) * H);
    const float4* smW4_2 = (const float4*)(smW + (w * 3 + 2) * H);
    // r5 source: smem for warps 0..2, global otherwise (warp-uniform pointer)
    const float4* src5 = (w < 3) ? (const float4*)(smW + (24 + w) * H) : wrow5;

    for (int t = 0; t < SEQ; ++t) {
        const int p = t & 1;

        // stage h_{t-1} into smem (must bypass L1: written by other SMs)
        {
            const float4* hsrc = (const float4*)g_h[p];
            float4 v0 = __ldcg(&hsrc[tid]);
            float4 v1 = __ldcg(&hsrc[tid + TPB]);
            ((float4*)smH)[tid]       = v0;
            ((float4*)smH)[tid + TPB] = v1;
        }
        if (tid == 0) s_x = __ldcg(&inputs[t]);
        __syncthreads();

        // ---- 8 row dot-products, h-outer so each h float4 is loaded once ----
        float4 acc[8];
        #pragma unroll
        for (int r = 0; r < 8; ++r) acc[r] = make_float4(0.f, 0.f, 0.f, 0.f);

        #pragma unroll
        for (int cc = 0; cc < 16; ++cc) {
            const int o = cc * 32 + lane;
            float4 hv = smH4[o];
            float4 wv[8];
            wv[0] = smW4_0[o];
            wv[1] = smW4_1[o];
            wv[2] = smW4_2[o];
            wv[3] = rw3q[cc];
            wv[4] = rw4q[cc];
            wv[5] = src5[o];
            wv[6] = __ldcg(&wrow6[o]);
            wv[7] = __ldcg(&wrow7[o]);
            #pragma unroll
            for (int r = 0; r < 8; ++r) {
                acc[r].x = fmaf(wv[r].x, hv.x, acc[r].x);
                acc[r].y = fmaf(wv[r].y, hv.y, acc[r].y);
                acc[r].z = fmaf(wv[r].z, hv.z, acc[r].z);
                acc[r].w = fmaf(wv[r].w, hv.w, acc[r].w);
            }
        }

        float rs[8];
        #pragma unroll
        for (int r = 0; r < 8; ++r) {
            float s = (acc[r].x + acc[r].y) + (acc[r].z + acc[r].w);
            #pragma unroll
            for (int o2 = 16; o2; o2 >>= 1)
                s += __shfl_xor_sync(0xffffffffu, s, o2);
            rs[r] = s;
        }

        // ---- gates: lane L in {0,1} owns unit ubase+L ----
        if (lane < 2) {
            float x  = s_x;
            float zi = (lane ? rs[4] : rs[0]) + x * wx0 + bb0;
            float zf = (lane ? rs[5] : rs[1]) + x * wx1 + bb1;
            float zg = (lane ? rs[6] : rs[2]) + x * wx2 + bb2;
            float zo = (lane ? rs[7] : rs[3]) + x * wx3 + bb3;
            float ig = sigm_f(zi);
            float fg = sigm_f(zf);
            float gg = tanh_f(zg);
            float og = sigm_f(zo);
            c_st = fg * c_st + ig * gg;
            float hn = og * tanh_f(c_st);
            h_last = hn;
            g_h[p ^ 1][ubase + lane] = hn;
            float py = wo * hn;
            py += __shfl_xor_sync(0x3u, py, 1);
            if (lane == 0) s_ypart[w] = py;
        }
        __syncthreads();

        // ---- publish h, partial y; grid barrier (proven R1 barrier) ----
        if (tid == 0) {
            float s = 0.f;
            #pragma unroll
            for (int i = 0; i < NWARP; ++i) s += s_ypart[i];
            g_py[(size_t)cta * SEQ + t] = s;

            __threadfence();
            unsigned tgt  = base_gen + 2 + (unsigned)t;
            unsigned prev = atomicAdd(&g_count, 1u);
            if (prev == NCTA - 1) { g_count = 0; __threadfence(); g_gen = tgt; }
            else { while (g_gen != tgt) __nanosleep(32); }
        }
        __syncthreads();
    }

    // final h, c
    if (lane < 2) {
        int ug = ubase + lane;
        out[SEQ + ug]     = h_last;
        out[SEQ + H + ug] = c_st;
    }
}

__global__ void reduce_y(const float* __restrict__ b_out, float* __restrict__ out)
{
    int t = blockIdx.x * blockDim.x + threadIdx.x;
    float s = b_out[0];
    #pragma unroll 8
    for (int b = 0; b < NCTA; ++b)
        s += g_py[(size_t)b * SEQ + t];   // fixed order -> deterministic
    out[t] = s;
}

extern "C" void kernel_launch(void* const* d_in, const int* in_sizes, int n_in,
                              void* d_out, int out_size)
{
    (void)in_sizes; (void)n_in; (void)out_size;
    const float* inputs = (const float*)d_in[0];
    const float* w_ih   = (const float*)d_in[1];
    const float* w_hh   = (const float*)d_in[2];
    const float* b_ih   = (const float*)d_in[3];
    const float* b_hh   = (const float*)d_in[4];
    const float* w_out  = (const float*)d_in[5];
    const float* b_out  = (const float*)d_in[6];
    float* out = (float*)d_out;

    cudaFuncSetAttribute(lstm_persistent,
                         cudaFuncAttributeMaxDynamicSharedMemorySize, SMEM_BYTES);

    lstm_persistent<<<NCTA, TPB, SMEM_BYTES>>>(inputs, w_ih, w_hh, b_ih, b_hh,
                                               w_out, out);
    reduce_y<<<SEQ / 256, 256>>>(b_out, out);
}